// round 1
// baseline (speedup 1.0000x reference)
#include <cuda_runtime.h>
#include <cuda_bf16.h>

// ---------------------------------------------------------------------------
// Problem constants
// ---------------------------------------------------------------------------
#define BATCH   4
#define SEQ     2048
#define CDIM    2048
#define NHEAD   16
#define HD      128           // head dim
#define QKVDIM  (3 * CDIM)    // 6144
#define MROWS   (BATCH * SEQ) // 8192

// Scratch buffers (device globals: allocation-free per harness rules)
__device__ float g_qkv[(size_t)MROWS * QKVDIM];   // [8192, 6144]
__device__ float g_y  [(size_t)MROWS * CDIM];     // [8192, 2048]

// ---------------------------------------------------------------------------
// SGEMM: C[M,N] = A[M,K] @ B[K,N], fp32, all dims multiples of tile sizes.
// 128x128 block tile, BK=16, 256 threads, 8x8 register tile per thread.
// ---------------------------------------------------------------------------
#define BM 128
#define BN 128
#define BK 16
#define TM 8
#define TN 8

__global__ __launch_bounds__(256, 2)
void sgemm_kernel(const float* __restrict__ A, const float* __restrict__ B,
                  float* __restrict__ C, int M, int N, int K)
{
    __shared__ float As[BK][BM];   // transposed A tile
    __shared__ float Bs[BK][BN];

    const int tid  = threadIdx.x;
    const int brow = blockIdx.y * BM;
    const int bcol = blockIdx.x * BN;
    const int trow = (tid / 16) * TM;
    const int tcol = (tid % 16) * TN;

    float acc[TM][TN];
    #pragma unroll
    for (int i = 0; i < TM; ++i)
        #pragma unroll
        for (int j = 0; j < TN; ++j) acc[i][j] = 0.0f;

    for (int k0 = 0; k0 < K; k0 += BK) {
        // Load A tile (128 rows x 16 k) -> transposed into As[k][m]
        #pragma unroll
        for (int q = 0; q < 2; ++q) {
            int idx = tid + q * 256;          // 0..511 float4 slots
            int r  = idx >> 2;                // 0..127
            int kc = (idx & 3) * 4;           // 0,4,8,12
            float4 v = *(const float4*)(A + (size_t)(brow + r) * K + k0 + kc);
            As[kc + 0][r] = v.x;
            As[kc + 1][r] = v.y;
            As[kc + 2][r] = v.z;
            As[kc + 3][r] = v.w;
        }
        // Load B tile (16 k x 128 cols), direct
        #pragma unroll
        for (int q = 0; q < 2; ++q) {
            int idx = tid + q * 256;
            int kr = idx >> 5;                // 0..15
            int nc = (idx & 31) * 4;          // 0..124
            *(float4*)(&Bs[kr][nc]) =
                *(const float4*)(B + (size_t)(k0 + kr) * N + bcol + nc);
        }
        __syncthreads();

        #pragma unroll
        for (int kk = 0; kk < BK; ++kk) {
            float af[TM], bf[TN];
            #pragma unroll
            for (int i = 0; i < TM; ++i) af[i] = As[kk][trow + i];
            #pragma unroll
            for (int j = 0; j < TN; ++j) bf[j] = Bs[kk][tcol + j];
            #pragma unroll
            for (int i = 0; i < TM; ++i)
                #pragma unroll
                for (int j = 0; j < TN; ++j)
                    acc[i][j] += af[i] * bf[j];
        }
        __syncthreads();
    }

    #pragma unroll
    for (int i = 0; i < TM; ++i)
        #pragma unroll
        for (int j = 0; j < TN; j += 4) {
            float4 v = make_float4(acc[i][j], acc[i][j+1], acc[i][j+2], acc[i][j+3]);
            *(float4*)(C + (size_t)(brow + trow + i) * N + bcol + tcol + j) = v;
        }
}

// ---------------------------------------------------------------------------
// Flash attention (fp32, causal).
// Block: one (b, h, q-tile of 64). 256 threads = 8 warps; warp w owns query
// rows w*8 .. w*8+7 exclusively -> softmax stats live in registers.
// K/V streamed in 64-row tiles; tiles strictly above the diagonal skipped.
// ---------------------------------------------------------------------------
#define BQ  64
#define BKT 64
#define HDP (HD + 4)    // padded row (keeps float4 alignment)
#define PSP (BKT + 2)

// dynamic smem layout (floats):
//   Qs[BQ][HDP] | Ks[BKT][HDP] | Vs[BKT][HDP] | Ps[BQ][PSP]
#define ATTN_SMEM_FLOATS (3 * BQ * HDP + BQ * PSP)
#define ATTN_SMEM_BYTES  (ATTN_SMEM_FLOATS * 4)

__global__ __launch_bounds__(256, 1)
void attn_kernel(const float* __restrict__ qkv, float* __restrict__ y)
{
    extern __shared__ float sm[];
    float (*Qs)[HDP] = (float (*)[HDP])(sm);
    float (*Ks)[HDP] = (float (*)[HDP])(sm + BQ * HDP);
    float (*Vs)[HDP] = (float (*)[HDP])(sm + 2 * BQ * HDP);
    float (*Ps)[PSP] = (float (*)[PSP])(sm + 3 * BQ * HDP);

    const int tid  = threadIdx.x;
    const int lane = tid & 31;
    const int warp = tid >> 5;
    const int qt   = (int)gridDim.x - 1 - (int)blockIdx.x;  // big tiles first
    const int h    = blockIdx.y;
    const int b    = blockIdx.z;

    const size_t tokStride = QKVDIM;
    const size_t base = (size_t)b * SEQ * tokStride + (size_t)h * HD;
    const float scale = 0.08838834764831845f;  // 1/sqrt(128)

    // Load Q tile, pre-scaled
    for (int i = tid; i < BQ * (HD / 4); i += 256) {
        int r  = i >> 5;
        int c4 = (i & 31) * 4;
        float4 v = *(const float4*)(qkv + base + (size_t)(qt * BQ + r) * tokStride + c4);
        float4 sv = make_float4(v.x * scale, v.y * scale, v.z * scale, v.w * scale);
        *(float4*)&Qs[r][c4] = sv;
    }

    float m_i[8], l_i[8], acc[8][4];
    #pragma unroll
    for (int i = 0; i < 8; ++i) {
        m_i[i] = -1e30f;
        l_i[i] = 0.0f;
        acc[i][0] = acc[i][1] = acc[i][2] = acc[i][3] = 0.0f;
    }
    const int r0   = warp * 8;
    const int c0   = lane * 2;
    const int dcol = lane * 4;

    __syncthreads();

    for (int kt = 0; kt <= qt; ++kt) {
        // Load K and V tiles
        for (int i = tid; i < BKT * (HD / 4); i += 256) {
            int r  = i >> 5;
            int c4 = (i & 31) * 4;
            size_t tok = (size_t)(kt * BKT + r) * tokStride;
            *(float4*)&Ks[r][c4] = *(const float4*)(qkv + base + CDIM     + tok + c4);
            *(float4*)&Vs[r][c4] = *(const float4*)(qkv + base + 2 * CDIM + tok + c4);
        }
        __syncthreads();

        // S = Q K^T (each thread: 8 rows x 2 key columns)
        float s[8][2];
        #pragma unroll
        for (int i = 0; i < 8; ++i) { s[i][0] = 0.0f; s[i][1] = 0.0f; }

        #pragma unroll 4
        for (int d4 = 0; d4 < HD; d4 += 4) {
            float4 k0 = *(const float4*)&Ks[c0][d4];
            float4 k1 = *(const float4*)&Ks[c0 + 1][d4];
            #pragma unroll
            for (int i = 0; i < 8; ++i) {
                float4 q = *(const float4*)&Qs[r0 + i][d4];
                s[i][0] += q.x * k0.x + q.y * k0.y + q.z * k0.z + q.w * k0.w;
                s[i][1] += q.x * k1.x + q.y * k1.y + q.z * k1.z + q.w * k1.w;
            }
        }

        // Online softmax update (warp owns its rows exclusively)
        const bool diag = (kt == qt);
        #pragma unroll
        for (int i = 0; i < 8; ++i) {
            float s0 = s[i][0], s1 = s[i][1];
            if (diag) {
                int r = r0 + i;
                if (c0     > r) s0 = -1e30f;
                if (c0 + 1 > r) s1 = -1e30f;
            }
            float mx = fmaxf(s0, s1);
            #pragma unroll
            for (int off = 16; off; off >>= 1)
                mx = fmaxf(mx, __shfl_xor_sync(0xffffffffu, mx, off));
            float m_new = fmaxf(m_i[i], mx);
            float p0 = __expf(s0 - m_new);
            float p1 = __expf(s1 - m_new);
            float rs = p0 + p1;
            #pragma unroll
            for (int off = 16; off; off >>= 1)
                rs += __shfl_xor_sync(0xffffffffu, rs, off);
            float corr = __expf(m_i[i] - m_new);
            m_i[i] = m_new;
            l_i[i] = l_i[i] * corr + rs;
            acc[i][0] *= corr; acc[i][1] *= corr;
            acc[i][2] *= corr; acc[i][3] *= corr;
            Ps[r0 + i][c0]     = p0;
            Ps[r0 + i][c0 + 1] = p1;
        }
        __syncwarp();

        // O += P @ V (each thread: 8 rows x 4 output dims)
        #pragma unroll 4
        for (int c = 0; c < BKT; ++c) {
            float4 v4 = *(const float4*)&Vs[c][dcol];
            #pragma unroll
            for (int i = 0; i < 8; ++i) {
                float p = Ps[r0 + i][c];
                acc[i][0] += p * v4.x;
                acc[i][1] += p * v4.y;
                acc[i][2] += p * v4.z;
                acc[i][3] += p * v4.w;
            }
        }
        __syncthreads();   // before next tile overwrites Ks/Vs
    }

    // Normalize and write y[b, t, h*HD + d]
    #pragma unroll
    for (int i = 0; i < 8; ++i) {
        float inv = 1.0f / l_i[i];
        float4 o = make_float4(acc[i][0] * inv, acc[i][1] * inv,
                               acc[i][2] * inv, acc[i][3] * inv);
        size_t row = (size_t)b * SEQ + qt * BQ + r0 + i;
        *(float4*)(y + row * CDIM + (size_t)h * HD + dcol) = o;
    }
}

// ---------------------------------------------------------------------------
// kernel_launch
// ---------------------------------------------------------------------------
extern "C" void kernel_launch(void* const* d_in, const int* in_sizes, int n_in,
                              void* d_out, int out_size)
{
    const float* x     = (const float*)d_in[0];   // [4,2048,2048]
    const float* Wqkv  = (const float*)d_in[1];   // [2048,6144]
    const float* Wproj = (const float*)d_in[2];   // [2048,2048]
    float* out = (float*)d_out;                   // [4,2048,2048]

    float* qkv = nullptr;
    float* y   = nullptr;
    cudaGetSymbolAddress((void**)&qkv, g_qkv);
    cudaGetSymbolAddress((void**)&y,   g_y);

    cudaFuncSetAttribute(attn_kernel,
                         cudaFuncAttributeMaxDynamicSharedMemorySize,
                         ATTN_SMEM_BYTES);

    // 1) qkv = x @ Wqkv     [8192,2048] x [2048,6144]
    sgemm_kernel<<<dim3(QKVDIM / BN, MROWS / BM), 256>>>(
        x, Wqkv, qkv, MROWS, QKVDIM, CDIM);

    // 2) attention -> y [8192,2048]
    attn_kernel<<<dim3(SEQ / BQ, NHEAD, BATCH), 256, ATTN_SMEM_BYTES>>>(qkv, y);

    // 3) out = y @ Wproj    [8192,2048] x [2048,2048]
    sgemm_kernel<<<dim3(CDIM / BN, MROWS / BM), 256>>>(
        y, Wproj, out, MROWS, CDIM, CDIM);
}

// round 3
// speedup vs baseline: 3.3703x; 3.3703x over previous
#include <cuda_runtime.h>
#include <cuda_bf16.h>
#include <cstdint>

// ---------------------------------------------------------------------------
// Problem constants
// ---------------------------------------------------------------------------
#define BATCH   4
#define SEQ     2048
#define CDIM    2048
#define NHEAD   16
#define HD      128
#define QKVDIM  (3 * CDIM)    // 6144
#define MROWS   (BATCH * SEQ) // 8192

__device__ float g_qkv[(size_t)MROWS * QKVDIM];   // [8192, 6144]
__device__ float g_y  [(size_t)MROWS * CDIM];     // [8192, 2048]

// ---------------------------------------------------------------------------
// TF32 tensor-core GEMM: C[M,N] = A[M,K] @ B[K,N]  (row-major, fp32 in/out)
// 128x128 block tile, BK=32, 256 threads (8 warps, 4x2), warp tile 32x64.
// mma.sync.aligned.m16n8k8.row.col.f32.tf32.tf32.f32
// cp.async double-buffered smem; cvt.rna.tf32 at fragment load.
// ---------------------------------------------------------------------------
#define BM 128
#define BN 128
#define BK 32
#define BKP 36    // A row pad -> conflict-free A-fragment LDS
#define BNP 136   // B row pad -> conflict-free B-fragment LDS

#define SMEM_A_FLOATS (BM * BKP)                  // 4608
#define SMEM_B_FLOATS (BK * BNP)                  // 4352
#define GEMM_SMEM_BYTES (2 * (SMEM_A_FLOATS + SMEM_B_FLOATS) * 4)  // 71680

__device__ __forceinline__ void cp_async16(void* smem_dst, const void* gmem_src) {
    uint32_t s = (uint32_t)__cvta_generic_to_shared(smem_dst);
    asm volatile("cp.async.cg.shared.global [%0], [%1], 16;\n" :: "r"(s), "l"(gmem_src));
}
__device__ __forceinline__ uint32_t f2tf(float x) {
    uint32_t r;
    asm("cvt.rna.tf32.f32 %0, %1;" : "=r"(r) : "f"(x));
    return r;
}
__device__ __forceinline__ void mma_tf32(float* d, const uint32_t* a, const uint32_t* b) {
    asm volatile(
        "mma.sync.aligned.m16n8k8.row.col.f32.tf32.tf32.f32 "
        "{%0,%1,%2,%3}, {%4,%5,%6,%7}, {%8,%9}, {%0,%1,%2,%3};"
        : "+f"(d[0]), "+f"(d[1]), "+f"(d[2]), "+f"(d[3])
        : "r"(a[0]), "r"(a[1]), "r"(a[2]), "r"(a[3]), "r"(b[0]), "r"(b[1]));
}

__global__ __launch_bounds__(256, 2)
void gemm_tf32(const float* __restrict__ A, const float* __restrict__ B,
               float* __restrict__ C, int M, int N, int K)
{
    extern __shared__ float sm[];
    float* AsBase = sm;                           // [2][BM][BKP]
    float* BsBase = sm + 2 * SMEM_A_FLOATS;       // [2][BK][BNP]

    const int tid  = threadIdx.x;
    const int lane = tid & 31;
    const int warp = tid >> 5;
    const int g    = lane >> 2;     // group id 0..7
    const int tig  = lane & 3;      // thread-in-group 0..3
    const int Wm   = (warp >> 1) * 32;
    const int Wn   = (warp & 1) * 64;
    const int brow = blockIdx.y * BM;
    const int bcol = blockIdx.x * BN;

    float acc[2][8][4];
    #pragma unroll
    for (int mt = 0; mt < 2; ++mt)
        #pragma unroll
        for (int nt = 0; nt < 8; ++nt)
            #pragma unroll
            for (int j = 0; j < 4; ++j) acc[mt][nt][j] = 0.0f;

    // tile loader: A 128x32 and B 32x128 via 16B cp.async (4+4 chunks/thread)
    auto load_tile = [&](int k0, int buf) {
        float* a_s = AsBase + buf * SMEM_A_FLOATS;
        float* b_s = BsBase + buf * SMEM_B_FLOATS;
        #pragma unroll
        for (int q = 0; q < 4; ++q) {
            int idx = tid + q * 256;          // 0..1023
            int r = idx >> 3;                 // 0..127
            int c = (idx & 7) * 4;            // 0..28
            cp_async16(a_s + r * BKP + c, A + (size_t)(brow + r) * K + k0 + c);
        }
        #pragma unroll
        for (int q = 0; q < 4; ++q) {
            int idx = tid + q * 256;
            int r = idx >> 5;                 // 0..31
            int c = (idx & 31) * 4;           // 0..124
            cp_async16(b_s + r * BNP + c, B + (size_t)(k0 + r) * N + bcol + c);
        }
        asm volatile("cp.async.commit_group;\n");
    };

    const int nIter = K / BK;
    load_tile(0, 0);

    for (int it = 0; it < nIter; ++it) {
        if (it + 1 < nIter) {
            load_tile((it + 1) * BK, (it + 1) & 1);
            asm volatile("cp.async.wait_group 1;\n");
        } else {
            asm volatile("cp.async.wait_group 0;\n");
        }
        __syncthreads();

        const float* a_s = AsBase + (it & 1) * SMEM_A_FLOATS;
        const float* b_s = BsBase + (it & 1) * SMEM_B_FLOATS;

        #pragma unroll
        for (int ks = 0; ks < 4; ++ks) {
            uint32_t af[2][4], bf[8][2];
            #pragma unroll
            for (int mt = 0; mt < 2; ++mt) {
                const float* p = a_s + (size_t)(Wm + mt * 16 + g) * BKP + ks * 8 + tig;
                af[mt][0] = f2tf(p[0]);
                af[mt][1] = f2tf(p[8 * BKP]);
                af[mt][2] = f2tf(p[4]);
                af[mt][3] = f2tf(p[8 * BKP + 4]);
            }
            #pragma unroll
            for (int nt = 0; nt < 8; ++nt) {
                const float* p = b_s + (size_t)(ks * 8 + tig) * BNP + Wn + nt * 8 + g;
                bf[nt][0] = f2tf(p[0]);
                bf[nt][1] = f2tf(p[4 * BNP]);
            }
            #pragma unroll
            for (int mt = 0; mt < 2; ++mt)
                #pragma unroll
                for (int nt = 0; nt < 8; ++nt)
                    mma_tf32(acc[mt][nt], af[mt], bf[nt]);
        }
        __syncthreads();
    }

    // writeback: c0/c1 at (row=g, col=tig*2), c2/c3 at row+8
    #pragma unroll
    for (int mt = 0; mt < 2; ++mt) {
        int row = brow + Wm + mt * 16 + g;
        #pragma unroll
        for (int nt = 0; nt < 8; ++nt) {
            int col = bcol + Wn + nt * 8 + tig * 2;
            float2 lo = make_float2(acc[mt][nt][0], acc[mt][nt][1]);
            float2 hi = make_float2(acc[mt][nt][2], acc[mt][nt][3]);
            *(float2*)(C + (size_t)row * N + col) = lo;
            *(float2*)(C + (size_t)(row + 8) * N + col) = hi;
        }
    }
}

// ---------------------------------------------------------------------------
// Flash attention (fp32, causal) — unchanged from R1 (exact, keeps total error low)
// ---------------------------------------------------------------------------
#define BQ  64
#define BKT 64
#define HDP (HD + 4)
#define PSP (BKT + 2)
#define ATTN_SMEM_FLOATS (3 * BQ * HDP + BQ * PSP)
#define ATTN_SMEM_BYTES  (ATTN_SMEM_FLOATS * 4)

__global__ __launch_bounds__(256, 1)
void attn_kernel(const float* __restrict__ qkv, float* __restrict__ y)
{
    extern __shared__ float sm[];
    float (*Qs)[HDP] = (float (*)[HDP])(sm);
    float (*Ks)[HDP] = (float (*)[HDP])(sm + BQ * HDP);
    float (*Vs)[HDP] = (float (*)[HDP])(sm + 2 * BQ * HDP);
    float (*Ps)[PSP] = (float (*)[PSP])(sm + 3 * BQ * HDP);

    const int tid  = threadIdx.x;
    const int lane = tid & 31;
    const int warp = tid >> 5;
    const int qt   = (int)gridDim.x - 1 - (int)blockIdx.x;
    const int h    = blockIdx.y;
    const int b    = blockIdx.z;

    const size_t tokStride = QKVDIM;
    const size_t base = (size_t)b * SEQ * tokStride + (size_t)h * HD;
    const float scale = 0.08838834764831845f;

    for (int i = tid; i < BQ * (HD / 4); i += 256) {
        int r  = i >> 5;
        int c4 = (i & 31) * 4;
        float4 v = *(const float4*)(qkv + base + (size_t)(qt * BQ + r) * tokStride + c4);
        float4 sv = make_float4(v.x * scale, v.y * scale, v.z * scale, v.w * scale);
        *(float4*)&Qs[r][c4] = sv;
    }

    float m_i[8], l_i[8], acc[8][4];
    #pragma unroll
    for (int i = 0; i < 8; ++i) {
        m_i[i] = -1e30f;
        l_i[i] = 0.0f;
        acc[i][0] = acc[i][1] = acc[i][2] = acc[i][3] = 0.0f;
    }
    const int r0   = warp * 8;
    const int c0   = lane * 2;
    const int dcol = lane * 4;

    __syncthreads();

    for (int kt = 0; kt <= qt; ++kt) {
        for (int i = tid; i < BKT * (HD / 4); i += 256) {
            int r  = i >> 5;
            int c4 = (i & 31) * 4;
            size_t tok = (size_t)(kt * BKT + r) * tokStride;
            *(float4*)&Ks[r][c4] = *(const float4*)(qkv + base + CDIM     + tok + c4);
            *(float4*)&Vs[r][c4] = *(const float4*)(qkv + base + 2 * CDIM + tok + c4);
        }
        __syncthreads();

        float s[8][2];
        #pragma unroll
        for (int i = 0; i < 8; ++i) { s[i][0] = 0.0f; s[i][1] = 0.0f; }

        #pragma unroll 4
        for (int d4 = 0; d4 < HD; d4 += 4) {
            float4 k0 = *(const float4*)&Ks[c0][d4];
            float4 k1 = *(const float4*)&Ks[c0 + 1][d4];
            #pragma unroll
            for (int i = 0; i < 8; ++i) {
                float4 q = *(const float4*)&Qs[r0 + i][d4];
                s[i][0] += q.x * k0.x + q.y * k0.y + q.z * k0.z + q.w * k0.w;
                s[i][1] += q.x * k1.x + q.y * k1.y + q.z * k1.z + q.w * k1.w;
            }
        }

        const bool diag = (kt == qt);
        #pragma unroll
        for (int i = 0; i < 8; ++i) {
            float s0 = s[i][0], s1 = s[i][1];
            if (diag) {
                int r = r0 + i;
                if (c0     > r) s0 = -1e30f;
                if (c0 + 1 > r) s1 = -1e30f;
            }
            float mx = fmaxf(s0, s1);
            #pragma unroll
            for (int off = 16; off; off >>= 1)
                mx = fmaxf(mx, __shfl_xor_sync(0xffffffffu, mx, off));
            float m_new = fmaxf(m_i[i], mx);
            float p0 = __expf(s0 - m_new);
            float p1 = __expf(s1 - m_new);
            float rs = p0 + p1;
            #pragma unroll
            for (int off = 16; off; off >>= 1)
                rs += __shfl_xor_sync(0xffffffffu, rs, off);
            float corr = __expf(m_i[i] - m_new);
            m_i[i] = m_new;
            l_i[i] = l_i[i] * corr + rs;
            acc[i][0] *= corr; acc[i][1] *= corr;
            acc[i][2] *= corr; acc[i][3] *= corr;
            Ps[r0 + i][c0]     = p0;
            Ps[r0 + i][c0 + 1] = p1;
        }
        __syncwarp();

        #pragma unroll 4
        for (int c = 0; c < BKT; ++c) {
            float4 v4 = *(const float4*)&Vs[c][dcol];
            #pragma unroll
            for (int i = 0; i < 8; ++i) {
                float p = Ps[r0 + i][c];
                acc[i][0] += p * v4.x;
                acc[i][1] += p * v4.y;
                acc[i][2] += p * v4.z;
                acc[i][3] += p * v4.w;
            }
        }
        __syncthreads();
    }

    #pragma unroll
    for (int i = 0; i < 8; ++i) {
        float inv = 1.0f / l_i[i];
        float4 o = make_float4(acc[i][0] * inv, acc[i][1] * inv,
                               acc[i][2] * inv, acc[i][3] * inv);
        size_t row = (size_t)b * SEQ + qt * BQ + r0 + i;
        *(float4*)(y + row * CDIM + (size_t)h * HD + dcol) = o;
    }
}

// ---------------------------------------------------------------------------
// kernel_launch
// ---------------------------------------------------------------------------
extern "C" void kernel_launch(void* const* d_in, const int* in_sizes, int n_in,
                              void* d_out, int out_size)
{
    const float* x     = (const float*)d_in[0];
    const float* Wqkv  = (const float*)d_in[1];
    const float* Wproj = (const float*)d_in[2];
    float* out = (float*)d_out;

    float* qkv = nullptr;
    float* y   = nullptr;
    cudaGetSymbolAddress((void**)&qkv, g_qkv);
    cudaGetSymbolAddress((void**)&y,   g_y);

    cudaFuncSetAttribute(gemm_tf32,
                         cudaFuncAttributeMaxDynamicSharedMemorySize,
                         GEMM_SMEM_BYTES);
    cudaFuncSetAttribute(attn_kernel,
                         cudaFuncAttributeMaxDynamicSharedMemorySize,
                         ATTN_SMEM_BYTES);

    // 1) qkv = x @ Wqkv   [8192,2048]x[2048,6144]
    gemm_tf32<<<dim3(QKVDIM / BN, MROWS / BM), 256, GEMM_SMEM_BYTES>>>(
        x, Wqkv, qkv, MROWS, QKVDIM, CDIM);

    // 2) attention -> y [8192,2048]
    attn_kernel<<<dim3(SEQ / BQ, NHEAD, BATCH), 256, ATTN_SMEM_BYTES>>>(qkv, y);

    // 3) out = y @ Wproj  [8192,2048]x[2048,2048]
    gemm_tf32<<<dim3(CDIM / BN, MROWS / BM), 256, GEMM_SMEM_BYTES>>>(
        y, Wproj, out, MROWS, CDIM, CDIM);
}

// round 4
// speedup vs baseline: 5.5501x; 1.6468x over previous
#include <cuda_runtime.h>
#include <cuda_bf16.h>
#include <cstdint>

// ---------------------------------------------------------------------------
// Problem constants
// ---------------------------------------------------------------------------
#define BATCH   4
#define SEQ     2048
#define CDIM    2048
#define NHEAD   16
#define HD      128
#define QKVDIM  (3 * CDIM)    // 6144
#define MROWS   (BATCH * SEQ) // 8192

__device__ float g_qkv[(size_t)MROWS * QKVDIM];   // [8192, 6144]
__device__ float g_y  [(size_t)MROWS * CDIM];     // [8192, 2048]

// ---------------------------------------------------------------------------
// Shared helpers
// ---------------------------------------------------------------------------
__device__ __forceinline__ void cp_async16(void* smem_dst, const void* gmem_src) {
    uint32_t s = (uint32_t)__cvta_generic_to_shared(smem_dst);
    asm volatile("cp.async.cg.shared.global [%0], [%1], 16;\n" :: "r"(s), "l"(gmem_src));
}
__device__ __forceinline__ uint32_t f2tf(float x) {
    uint32_t r;
    asm("cvt.rna.tf32.f32 %0, %1;" : "=r"(r) : "f"(x));
    return r;
}
__device__ __forceinline__ float f2tf_f(float x) {
    float r;
    asm("cvt.rna.tf32.f32 %0, %1;" : "=f"(r) : "f"(x));
    return r;
}
__device__ __forceinline__ void mma_tf32(float* d, const uint32_t* a, const uint32_t* b) {
    asm volatile(
        "mma.sync.aligned.m16n8k8.row.col.f32.tf32.tf32.f32 "
        "{%0,%1,%2,%3}, {%4,%5,%6,%7}, {%8,%9}, {%0,%1,%2,%3};"
        : "+f"(d[0]), "+f"(d[1]), "+f"(d[2]), "+f"(d[3])
        : "r"(a[0]), "r"(a[1]), "r"(a[2]), "r"(a[3]), "r"(b[0]), "r"(b[1]));
}

// ---------------------------------------------------------------------------
// TF32 tensor-core GEMM (unchanged from R3 — proven)
// ---------------------------------------------------------------------------
#define BM 128
#define BN 128
#define BK 32
#define BKP 36
#define BNP 136

#define SMEM_A_FLOATS (BM * BKP)
#define SMEM_B_FLOATS (BK * BNP)
#define GEMM_SMEM_BYTES (2 * (SMEM_A_FLOATS + SMEM_B_FLOATS) * 4)

__global__ __launch_bounds__(256, 2)
void gemm_tf32(const float* __restrict__ A, const float* __restrict__ B,
               float* __restrict__ C, int M, int N, int K)
{
    extern __shared__ float sm[];
    float* AsBase = sm;
    float* BsBase = sm + 2 * SMEM_A_FLOATS;

    const int tid  = threadIdx.x;
    const int lane = tid & 31;
    const int warp = tid >> 5;
    const int g    = lane >> 2;
    const int tig  = lane & 3;
    const int Wm   = (warp >> 1) * 32;
    const int Wn   = (warp & 1) * 64;
    const int brow = blockIdx.y * BM;
    const int bcol = blockIdx.x * BN;

    float acc[2][8][4];
    #pragma unroll
    for (int mt = 0; mt < 2; ++mt)
        #pragma unroll
        for (int nt = 0; nt < 8; ++nt)
            #pragma unroll
            for (int j = 0; j < 4; ++j) acc[mt][nt][j] = 0.0f;

    auto load_tile = [&](int k0, int buf) {
        float* a_s = AsBase + buf * SMEM_A_FLOATS;
        float* b_s = BsBase + buf * SMEM_B_FLOATS;
        #pragma unroll
        for (int q = 0; q < 4; ++q) {
            int idx = tid + q * 256;
            int r = idx >> 3;
            int c = (idx & 7) * 4;
            cp_async16(a_s + r * BKP + c, A + (size_t)(brow + r) * K + k0 + c);
        }
        #pragma unroll
        for (int q = 0; q < 4; ++q) {
            int idx = tid + q * 256;
            int r = idx >> 5;
            int c = (idx & 31) * 4;
            cp_async16(b_s + r * BNP + c, B + (size_t)(k0 + r) * N + bcol + c);
        }
        asm volatile("cp.async.commit_group;\n");
    };

    const int nIter = K / BK;
    load_tile(0, 0);

    for (int it = 0; it < nIter; ++it) {
        if (it + 1 < nIter) {
            load_tile((it + 1) * BK, (it + 1) & 1);
            asm volatile("cp.async.wait_group 1;\n");
        } else {
            asm volatile("cp.async.wait_group 0;\n");
        }
        __syncthreads();

        const float* a_s = AsBase + (it & 1) * SMEM_A_FLOATS;
        const float* b_s = BsBase + (it & 1) * SMEM_B_FLOATS;

        #pragma unroll
        for (int ks = 0; ks < 4; ++ks) {
            uint32_t af[2][4], bf[8][2];
            #pragma unroll
            for (int mt = 0; mt < 2; ++mt) {
                const float* p = a_s + (size_t)(Wm + mt * 16 + g) * BKP + ks * 8 + tig;
                af[mt][0] = f2tf(p[0]);
                af[mt][1] = f2tf(p[8 * BKP]);
                af[mt][2] = f2tf(p[4]);
                af[mt][3] = f2tf(p[8 * BKP + 4]);
            }
            #pragma unroll
            for (int nt = 0; nt < 8; ++nt) {
                const float* p = b_s + (size_t)(ks * 8 + tig) * BNP + Wn + nt * 8 + g;
                bf[nt][0] = f2tf(p[0]);
                bf[nt][1] = f2tf(p[4 * BNP]);
            }
            #pragma unroll
            for (int mt = 0; mt < 2; ++mt)
                #pragma unroll
                for (int nt = 0; nt < 8; ++nt)
                    mma_tf32(acc[mt][nt], af[mt], bf[nt]);
        }
        __syncthreads();
    }

    #pragma unroll
    for (int mt = 0; mt < 2; ++mt) {
        int row = brow + Wm + mt * 16 + g;
        #pragma unroll
        for (int nt = 0; nt < 8; ++nt) {
            int col = bcol + Wn + nt * 8 + tig * 2;
            float2 lo = make_float2(acc[mt][nt][0], acc[mt][nt][1]);
            float2 hi = make_float2(acc[mt][nt][2], acc[mt][nt][3]);
            *(float2*)(C + (size_t)row * N + col) = lo;
            *(float2*)(C + (size_t)(row + 8) * N + col) = hi;
        }
    }
}

// ---------------------------------------------------------------------------
// Tensor-core flash attention (tf32 mma, causal).
// Block = (b, h, 128-query tile). 8 warps; warp w owns query rows w*16..+15.
// S = Q K^T and O += P V via m16n8k8; softmax stats in registers.
// ---------------------------------------------------------------------------
#define ABQ 128
#define ABK 64
#define KP  132   // Ks pitch: bank(4g+tig) conflict-free B-frag loads
#define VP  136   // Vs pitch: bank(8tig+g) conflict-free B-frag loads
#define PP  68    // Ps pitch

#define ATTN_SMEM_FLOATS (ABK * KP + ABK * VP + ABQ * PP)
#define ATTN_SMEM_BYTES  (ATTN_SMEM_FLOATS * 4)   // ~103 KB

__global__ __launch_bounds__(256, 1)
void attn_tc(const float* __restrict__ qkv, float* __restrict__ y)
{
    extern __shared__ float sm[];
    float* Ks = sm;                       // [ABK][KP]
    float* Vs = sm + ABK * KP;            // [ABK][VP]
    float* Ps = sm + ABK * KP + ABK * VP; // [ABQ][PP]

    const int tid  = threadIdx.x;
    const int lane = tid & 31;
    const int warp = tid >> 5;
    const int g    = lane >> 2;
    const int tig  = lane & 3;
    const int qt   = (int)gridDim.x - 1 - (int)blockIdx.x;  // big tiles first
    const int h    = blockIdx.y;
    const int b    = blockIdx.z;

    const size_t base  = (size_t)b * SEQ * QKVDIM + (size_t)h * HD;
    const float  scale = 0.08838834764831845f;  // 1/sqrt(128)
    const int    r0    = warp * 16;

    // ---- Stage Q tile into smem (reuses Ks+Vs region), build A-frags in regs
    uint32_t qf[16][4];
    {
        float* QST = sm;  // [ABQ][KP], fits inside Ks+Vs region
        for (int i = tid; i < ABQ * 32; i += 256) {
            int r = i >> 5, c4 = (i & 31) * 4;
            float4 v = *(const float4*)(qkv + base + (size_t)(qt * ABQ + r) * QKVDIM + c4);
            *(float4*)(QST + r * KP + c4) = v;
        }
        __syncthreads();
        #pragma unroll
        for (int ks = 0; ks < 16; ++ks) {
            int c = ks * 8 + tig;
            qf[ks][0] = f2tf(QST[(r0 + g)     * KP + c]     * scale);
            qf[ks][1] = f2tf(QST[(r0 + g + 8) * KP + c]     * scale);
            qf[ks][2] = f2tf(QST[(r0 + g)     * KP + c + 4] * scale);
            qf[ks][3] = f2tf(QST[(r0 + g + 8) * KP + c + 4] * scale);
        }
        __syncthreads();
    }

    float of[16][4];
    #pragma unroll
    for (int nb = 0; nb < 16; ++nb)
        #pragma unroll
        for (int j = 0; j < 4; ++j) of[nb][j] = 0.0f;

    float m0 = -1e30f, m1 = -1e30f, l0 = 0.0f, l1 = 0.0f;
    const int rowg0 = qt * ABQ + r0 + g;     // global row of "g" rows
    const int rowg1 = rowg0 + 8;
    const int rowmax = qt * ABQ + r0 + 15;   // max row this warp owns
    const int ktmax = 2 * qt + 1;

    for (int kt = 0; kt <= ktmax; ++kt) {
        // Load K/V tiles, tf32-rounded at store time (cheap: 64 cvt/thread)
        for (int i = tid; i < ABK * 32; i += 256) {
            int r = i >> 5, c4 = (i & 31) * 4;
            size_t tok = (size_t)(kt * ABK + r) * QKVDIM;
            float4 kv = *(const float4*)(qkv + base + CDIM     + tok + c4);
            float4 vv = *(const float4*)(qkv + base + 2 * CDIM + tok + c4);
            float4 kr = make_float4(f2tf_f(kv.x), f2tf_f(kv.y), f2tf_f(kv.z), f2tf_f(kv.w));
            float4 vr = make_float4(f2tf_f(vv.x), f2tf_f(vv.y), f2tf_f(vv.z), f2tf_f(vv.w));
            *(float4*)(Ks + r * KP + c4) = kr;
            *(float4*)(Vs + r * VP + c4) = vr;
        }
        __syncthreads();

        const int colbase = kt * ABK;
        const bool skip = colbase > rowmax;   // warp fully above diagonal

        if (!skip) {
            // ---- S = Q K^T : warp tile 16x64
            float sf[8][4];
            #pragma unroll
            for (int nb = 0; nb < 8; ++nb)
                #pragma unroll
                for (int j = 0; j < 4; ++j) sf[nb][j] = 0.0f;

            #pragma unroll
            for (int ks = 0; ks < 16; ++ks) {
                uint32_t bf[8][2];
                #pragma unroll
                for (int nb = 0; nb < 8; ++nb) {
                    const float* p = Ks + (nb * 8 + g) * KP + ks * 8 + tig;
                    bf[nb][0] = __float_as_uint(p[0]);   // already tf32-rounded
                    bf[nb][1] = __float_as_uint(p[4]);
                }
                #pragma unroll
                for (int nb = 0; nb < 8; ++nb)
                    mma_tf32(sf[nb], qf[ks], bf[nb]);
            }

            // ---- causal mask (only tiles straddling the diagonal)
            if (colbase + ABK - 1 > rowg0) {
                #pragma unroll
                for (int nb = 0; nb < 8; ++nb) {
                    int col = colbase + nb * 8 + 2 * tig;
                    if (col     > rowg0) sf[nb][0] = -1e30f;
                    if (col + 1 > rowg0) sf[nb][1] = -1e30f;
                    if (col     > rowg1) sf[nb][2] = -1e30f;
                    if (col + 1 > rowg1) sf[nb][3] = -1e30f;
                }
            }

            // ---- online softmax (rows g and g+8; reduce over 4-lane tig group)
            float mx0 = -1e30f, mx1 = -1e30f;
            #pragma unroll
            for (int nb = 0; nb < 8; ++nb) {
                mx0 = fmaxf(mx0, fmaxf(sf[nb][0], sf[nb][1]));
                mx1 = fmaxf(mx1, fmaxf(sf[nb][2], sf[nb][3]));
            }
            mx0 = fmaxf(mx0, __shfl_xor_sync(0xffffffffu, mx0, 1));
            mx0 = fmaxf(mx0, __shfl_xor_sync(0xffffffffu, mx0, 2));
            mx1 = fmaxf(mx1, __shfl_xor_sync(0xffffffffu, mx1, 1));
            mx1 = fmaxf(mx1, __shfl_xor_sync(0xffffffffu, mx1, 2));

            float nm0 = fmaxf(m0, mx0);
            float nm1 = fmaxf(m1, mx1);
            float cr0 = __expf(m0 - nm0);
            float cr1 = __expf(m1 - nm1);

            float rs0 = 0.0f, rs1 = 0.0f;
            #pragma unroll
            for (int nb = 0; nb < 8; ++nb) {
                float e0 = __expf(sf[nb][0] - nm0);
                float e1 = __expf(sf[nb][1] - nm0);
                float e2 = __expf(sf[nb][2] - nm1);
                float e3 = __expf(sf[nb][3] - nm1);
                rs0 += e0 + e1;
                rs1 += e2 + e3;
                // store tf32-rounded P (A-frag reads skip cvt)
                *(float2*)(Ps + (r0 + g)     * PP + nb * 8 + 2 * tig) =
                    make_float2(f2tf_f(e0), f2tf_f(e1));
                *(float2*)(Ps + (r0 + g + 8) * PP + nb * 8 + 2 * tig) =
                    make_float2(f2tf_f(e2), f2tf_f(e3));
            }
            rs0 += __shfl_xor_sync(0xffffffffu, rs0, 1);
            rs0 += __shfl_xor_sync(0xffffffffu, rs0, 2);
            rs1 += __shfl_xor_sync(0xffffffffu, rs1, 1);
            rs1 += __shfl_xor_sync(0xffffffffu, rs1, 2);

            m0 = nm0; m1 = nm1;
            l0 = l0 * cr0 + rs0;
            l1 = l1 * cr1 + rs1;

            #pragma unroll
            for (int nb = 0; nb < 16; ++nb) {
                of[nb][0] *= cr0; of[nb][1] *= cr0;
                of[nb][2] *= cr1; of[nb][3] *= cr1;
            }
            __syncwarp();

            // ---- O += P V : k=64 (8 ksteps), n=128 (16 nblocks)
            #pragma unroll
            for (int ks2 = 0; ks2 < 8; ++ks2) {
                uint32_t pa[4];
                pa[0] = __float_as_uint(Ps[(r0 + g)     * PP + ks2 * 8 + tig]);
                pa[1] = __float_as_uint(Ps[(r0 + g + 8) * PP + ks2 * 8 + tig]);
                pa[2] = __float_as_uint(Ps[(r0 + g)     * PP + ks2 * 8 + tig + 4]);
                pa[3] = __float_as_uint(Ps[(r0 + g + 8) * PP + ks2 * 8 + tig + 4]);
                #pragma unroll
                for (int nb = 0; nb < 16; ++nb) {
                    uint32_t vb[2];
                    vb[0] = __float_as_uint(Vs[(ks2 * 8 + tig)     * VP + nb * 8 + g]);
                    vb[1] = __float_as_uint(Vs[(ks2 * 8 + tig + 4) * VP + nb * 8 + g]);
                    mma_tf32(of[nb], pa, vb);
                }
            }
            __syncwarp();
        }
        __syncthreads();   // before next tile overwrites Ks/Vs
    }

    // ---- normalize and write y
    float inv0 = 1.0f / l0;
    float inv1 = 1.0f / l1;
    size_t yrow0 = (size_t)b * SEQ + rowg0;
    size_t yrow1 = (size_t)b * SEQ + rowg1;
    #pragma unroll
    for (int nb = 0; nb < 16; ++nb) {
        int col = h * HD + nb * 8 + 2 * tig;
        *(float2*)(y + yrow0 * CDIM + col) =
            make_float2(of[nb][0] * inv0, of[nb][1] * inv0);
        *(float2*)(y + yrow1 * CDIM + col) =
            make_float2(of[nb][2] * inv1, of[nb][3] * inv1);
    }
}

// ---------------------------------------------------------------------------
// kernel_launch
// ---------------------------------------------------------------------------
extern "C" void kernel_launch(void* const* d_in, const int* in_sizes, int n_in,
                              void* d_out, int out_size)
{
    const float* x     = (const float*)d_in[0];
    const float* Wqkv  = (const float*)d_in[1];
    const float* Wproj = (const float*)d_in[2];
    float* out = (float*)d_out;

    float* qkv = nullptr;
    float* y   = nullptr;
    cudaGetSymbolAddress((void**)&qkv, g_qkv);
    cudaGetSymbolAddress((void**)&y,   g_y);

    cudaFuncSetAttribute(gemm_tf32,
                         cudaFuncAttributeMaxDynamicSharedMemorySize,
                         GEMM_SMEM_BYTES);
    cudaFuncSetAttribute(attn_tc,
                         cudaFuncAttributeMaxDynamicSharedMemorySize,
                         ATTN_SMEM_BYTES);

    // 1) qkv = x @ Wqkv   [8192,2048]x[2048,6144]
    gemm_tf32<<<dim3(QKVDIM / BN, MROWS / BM), 256, GEMM_SMEM_BYTES>>>(
        x, Wqkv, qkv, MROWS, QKVDIM, CDIM);

    // 2) attention -> y [8192,2048]
    attn_tc<<<dim3(SEQ / ABQ, NHEAD, BATCH), 256, ATTN_SMEM_BYTES>>>(qkv, y);

    // 3) out = y @ Wproj  [8192,2048]x[2048,2048]
    gemm_tf32<<<dim3(CDIM / BN, MROWS / BM), 256, GEMM_SMEM_BYTES>>>(
        y, Wproj, out, MROWS, CDIM, CDIM);
}

// round 5
// speedup vs baseline: 5.9853x; 1.0784x over previous
#include <cuda_runtime.h>
#include <cuda_bf16.h>
#include <cstdint>

// ---------------------------------------------------------------------------
// Problem constants
// ---------------------------------------------------------------------------
#define BATCH   4
#define SEQ     2048
#define CDIM    2048
#define NHEAD   16
#define HD      128
#define QKVDIM  (3 * CDIM)    // 6144
#define MROWS   (BATCH * SEQ) // 8192

__device__ float g_qkv [(size_t)MROWS * QKVDIM];   // [8192, 6144] (tf32-rounded)
__device__ float g_y   [(size_t)MROWS * CDIM];     // [8192, 2048] (tf32-rounded)
__device__ float g_xtf [(size_t)MROWS * CDIM];     // x rounded
__device__ float g_wqkv[(size_t)CDIM * QKVDIM];    // Wqkv rounded
__device__ float g_wprj[(size_t)CDIM * CDIM];      // Wproj rounded

// ---------------------------------------------------------------------------
// Helpers
// ---------------------------------------------------------------------------
__device__ __forceinline__ void cp_async16(void* smem_dst, const void* gmem_src) {
    uint32_t s = (uint32_t)__cvta_generic_to_shared(smem_dst);
    asm volatile("cp.async.cg.shared.global [%0], [%1], 16;\n" :: "r"(s), "l"(gmem_src));
}
__device__ __forceinline__ float f2tf_f(float x) {
    float r;
    asm("cvt.rna.tf32.f32 %0, %1;" : "=f"(r) : "f"(x));
    return r;
}
__device__ __forceinline__ uint32_t f2tf(float x) {
    uint32_t r;
    asm("cvt.rna.tf32.f32 %0, %1;" : "=r"(r) : "f"(x));
    return r;
}
__device__ __forceinline__ void mma_tf32(float* d, const uint32_t* a, const uint32_t* b) {
    asm volatile(
        "mma.sync.aligned.m16n8k8.row.col.f32.tf32.tf32.f32 "
        "{%0,%1,%2,%3}, {%4,%5,%6,%7}, {%8,%9}, {%0,%1,%2,%3};"
        : "+f"(d[0]), "+f"(d[1]), "+f"(d[2]), "+f"(d[3])
        : "r"(a[0]), "r"(a[1]), "r"(a[2]), "r"(a[3]), "r"(b[0]), "r"(b[1]));
}

// ---------------------------------------------------------------------------
// Prepass: round fp32 buffer to tf32 (vectorized)
// ---------------------------------------------------------------------------
__global__ void round_tf32(const float* __restrict__ src, float* __restrict__ dst,
                           int n4)
{
    int i = blockIdx.x * blockDim.x + threadIdx.x;
    if (i < n4) {
        float4 v = ((const float4*)src)[i];
        ((float4*)dst)[i] = make_float4(f2tf_f(v.x), f2tf_f(v.y),
                                        f2tf_f(v.z), f2tf_f(v.w));
    }
}

// ---------------------------------------------------------------------------
// TF32 tensor-core GEMM — operands pre-rounded, no cvt in mainloop.
// ROUND_C: round output to tf32 at writeback (for qkv feeding attention).
// ---------------------------------------------------------------------------
#define BM 128
#define BN 128
#define BK 32
#define BKP 36
#define BNP 136

#define SMEM_A_FLOATS (BM * BKP)
#define SMEM_B_FLOATS (BK * BNP)
#define GEMM_SMEM_BYTES (2 * (SMEM_A_FLOATS + SMEM_B_FLOATS) * 4)

template<bool ROUND_C>
__global__ __launch_bounds__(256, 2)
void gemm_tf32(const float* __restrict__ A, const float* __restrict__ B,
               float* __restrict__ C, int M, int N, int K)
{
    extern __shared__ float sm[];
    float* AsBase = sm;
    float* BsBase = sm + 2 * SMEM_A_FLOATS;

    const int tid  = threadIdx.x;
    const int lane = tid & 31;
    const int warp = tid >> 5;
    const int g    = lane >> 2;
    const int tig  = lane & 3;
    const int Wm   = (warp >> 1) * 32;
    const int Wn   = (warp & 1) * 64;
    const int brow = blockIdx.y * BM;
    const int bcol = blockIdx.x * BN;

    float acc[2][8][4];
    #pragma unroll
    for (int mt = 0; mt < 2; ++mt)
        #pragma unroll
        for (int nt = 0; nt < 8; ++nt)
            #pragma unroll
            for (int j = 0; j < 4; ++j) acc[mt][nt][j] = 0.0f;

    auto load_tile = [&](int k0, int buf) {
        float* a_s = AsBase + buf * SMEM_A_FLOATS;
        float* b_s = BsBase + buf * SMEM_B_FLOATS;
        #pragma unroll
        for (int q = 0; q < 4; ++q) {
            int idx = tid + q * 256;
            int r = idx >> 3;
            int c = (idx & 7) * 4;
            cp_async16(a_s + r * BKP + c, A + (size_t)(brow + r) * K + k0 + c);
        }
        #pragma unroll
        for (int q = 0; q < 4; ++q) {
            int idx = tid + q * 256;
            int r = idx >> 5;
            int c = (idx & 31) * 4;
            cp_async16(b_s + r * BNP + c, B + (size_t)(k0 + r) * N + bcol + c);
        }
        asm volatile("cp.async.commit_group;\n");
    };

    const int nIter = K / BK;
    load_tile(0, 0);

    for (int it = 0; it < nIter; ++it) {
        if (it + 1 < nIter) {
            load_tile((it + 1) * BK, (it + 1) & 1);
            asm volatile("cp.async.wait_group 1;\n");
        } else {
            asm volatile("cp.async.wait_group 0;\n");
        }
        __syncthreads();

        const float* a_s = AsBase + (it & 1) * SMEM_A_FLOATS;
        const float* b_s = BsBase + (it & 1) * SMEM_B_FLOATS;

        #pragma unroll
        for (int ks = 0; ks < 4; ++ks) {
            uint32_t af[2][4], bf[8][2];
            #pragma unroll
            for (int mt = 0; mt < 2; ++mt) {
                const float* p = a_s + (size_t)(Wm + mt * 16 + g) * BKP + ks * 8 + tig;
                af[mt][0] = __float_as_uint(p[0]);
                af[mt][1] = __float_as_uint(p[8 * BKP]);
                af[mt][2] = __float_as_uint(p[4]);
                af[mt][3] = __float_as_uint(p[8 * BKP + 4]);
            }
            #pragma unroll
            for (int nt = 0; nt < 8; ++nt) {
                const float* p = b_s + (size_t)(ks * 8 + tig) * BNP + Wn + nt * 8 + g;
                bf[nt][0] = __float_as_uint(p[0]);
                bf[nt][1] = __float_as_uint(p[4 * BNP]);
            }
            #pragma unroll
            for (int mt = 0; mt < 2; ++mt)
                #pragma unroll
                for (int nt = 0; nt < 8; ++nt)
                    mma_tf32(acc[mt][nt], af[mt], bf[nt]);
        }
        __syncthreads();
    }

    #pragma unroll
    for (int mt = 0; mt < 2; ++mt) {
        int row = brow + Wm + mt * 16 + g;
        #pragma unroll
        for (int nt = 0; nt < 8; ++nt) {
            int col = bcol + Wn + nt * 8 + tig * 2;
            float v0 = acc[mt][nt][0], v1 = acc[mt][nt][1];
            float v2 = acc[mt][nt][2], v3 = acc[mt][nt][3];
            if (ROUND_C) {
                v0 = f2tf_f(v0); v1 = f2tf_f(v1);
                v2 = f2tf_f(v2); v3 = f2tf_f(v3);
            }
            *(float2*)(C + (size_t)row * N + col) = make_float2(v0, v1);
            *(float2*)(C + (size_t)(row + 8) * N + col) = make_float2(v2, v3);
        }
    }
}

// ---------------------------------------------------------------------------
// Tensor-core flash attention (tf32 mma, causal), cp.async double-buffered K/V.
// qkv arrives tf32-rounded -> no cvt needed on K/V path.
// ---------------------------------------------------------------------------
#define ABQ 128
#define ABK 64
#define KP  132
#define VP  136
#define PP  68
#define SKV (ABK * KP + ABK * VP)          // one K/V buffer (17152 floats)

#define ATTN_SMEM_FLOATS (2 * SKV + ABQ * PP)
#define ATTN_SMEM_BYTES  (ATTN_SMEM_FLOATS * 4)   // 172 KB

__global__ __launch_bounds__(256, 1)
void attn_tc(const float* __restrict__ qkv, float* __restrict__ y)
{
    extern __shared__ float sm[];
    float* Ps = sm + 2 * SKV;  // [ABQ][PP]

    const int tid  = threadIdx.x;
    const int lane = tid & 31;
    const int warp = tid >> 5;
    const int g    = lane >> 2;
    const int tig  = lane & 3;
    const int qt   = (int)gridDim.x - 1 - (int)blockIdx.x;
    const int h    = blockIdx.y;
    const int b    = blockIdx.z;

    const size_t base  = (size_t)b * SEQ * QKVDIM + (size_t)h * HD;
    const float  scale = 0.08838834764831845f;
    const int    r0    = warp * 16;

    // ---- Stage Q tile into smem (reuses buf0 region), build A-frags in regs
    uint32_t qf[16][4];
    {
        float* QST = sm;  // [ABQ][KP] fits in buf0 (16896 < 17152)
        for (int i = tid; i < ABQ * 32; i += 256) {
            int r = i >> 5, c4 = (i & 31) * 4;
            float4 v = *(const float4*)(qkv + base + (size_t)(qt * ABQ + r) * QKVDIM + c4);
            *(float4*)(QST + r * KP + c4) = v;
        }
        __syncthreads();
        #pragma unroll
        for (int ks = 0; ks < 16; ++ks) {
            int c = ks * 8 + tig;
            qf[ks][0] = f2tf(QST[(r0 + g)     * KP + c]     * scale);
            qf[ks][1] = f2tf(QST[(r0 + g + 8) * KP + c]     * scale);
            qf[ks][2] = f2tf(QST[(r0 + g)     * KP + c + 4] * scale);
            qf[ks][3] = f2tf(QST[(r0 + g + 8) * KP + c + 4] * scale);
        }
        __syncthreads();
    }

    float of[16][4];
    #pragma unroll
    for (int nb = 0; nb < 16; ++nb)
        #pragma unroll
        for (int j = 0; j < 4; ++j) of[nb][j] = 0.0f;

    float m0 = -1e30f, m1 = -1e30f, l0 = 0.0f, l1 = 0.0f;
    const int rowg0  = qt * ABQ + r0 + g;
    const int rowg1  = rowg0 + 8;
    const int rowmax = qt * ABQ + r0 + 15;
    const int ktmax  = 2 * qt + 1;

    // cp.async K/V tile loader (no cvt: data pre-rounded)
    auto load_kv = [&](int kt, int buf) {
        float* Kd = sm + buf * SKV;
        float* Vd = Kd + ABK * KP;
        #pragma unroll
        for (int q = 0; q < 8; ++q) {
            int i = tid + q * 256;          // 0..2047
            int r = i >> 5, c4 = (i & 31) * 4;
            size_t tok = (size_t)(kt * ABK + r) * QKVDIM;
            cp_async16(Kd + r * KP + c4, qkv + base + CDIM     + tok + c4);
            cp_async16(Vd + r * VP + c4, qkv + base + 2 * CDIM + tok + c4);
        }
        asm volatile("cp.async.commit_group;\n");
    };

    load_kv(0, 0);

    for (int kt = 0; kt <= ktmax; ++kt) {
        if (kt + 1 <= ktmax) {
            load_kv(kt + 1, (kt + 1) & 1);
            asm volatile("cp.async.wait_group 1;\n");
        } else {
            asm volatile("cp.async.wait_group 0;\n");
        }
        __syncthreads();

        const float* Ks = sm + (kt & 1) * SKV;
        const float* Vs = Ks + ABK * KP;

        const int colbase = kt * ABK;
        const bool skip = colbase > rowmax;

        if (!skip) {
            // ---- S = Q K^T : warp tile 16x64
            float sf[8][4];
            #pragma unroll
            for (int nb = 0; nb < 8; ++nb)
                #pragma unroll
                for (int j = 0; j < 4; ++j) sf[nb][j] = 0.0f;

            #pragma unroll
            for (int ks = 0; ks < 16; ++ks) {
                uint32_t bf[8][2];
                #pragma unroll
                for (int nb = 0; nb < 8; ++nb) {
                    const float* p = Ks + (nb * 8 + g) * KP + ks * 8 + tig;
                    bf[nb][0] = __float_as_uint(p[0]);
                    bf[nb][1] = __float_as_uint(p[4]);
                }
                #pragma unroll
                for (int nb = 0; nb < 8; ++nb)
                    mma_tf32(sf[nb], qf[ks], bf[nb]);
            }

            // ---- causal mask
            if (colbase + ABK - 1 > rowg0) {
                #pragma unroll
                for (int nb = 0; nb < 8; ++nb) {
                    int col = colbase + nb * 8 + 2 * tig;
                    if (col     > rowg0) sf[nb][0] = -1e30f;
                    if (col + 1 > rowg0) sf[nb][1] = -1e30f;
                    if (col     > rowg1) sf[nb][2] = -1e30f;
                    if (col + 1 > rowg1) sf[nb][3] = -1e30f;
                }
            }

            // ---- online softmax
            float mx0 = -1e30f, mx1 = -1e30f;
            #pragma unroll
            for (int nb = 0; nb < 8; ++nb) {
                mx0 = fmaxf(mx0, fmaxf(sf[nb][0], sf[nb][1]));
                mx1 = fmaxf(mx1, fmaxf(sf[nb][2], sf[nb][3]));
            }
            mx0 = fmaxf(mx0, __shfl_xor_sync(0xffffffffu, mx0, 1));
            mx0 = fmaxf(mx0, __shfl_xor_sync(0xffffffffu, mx0, 2));
            mx1 = fmaxf(mx1, __shfl_xor_sync(0xffffffffu, mx1, 1));
            mx1 = fmaxf(mx1, __shfl_xor_sync(0xffffffffu, mx1, 2));

            float nm0 = fmaxf(m0, mx0);
            float nm1 = fmaxf(m1, mx1);
            float cr0 = __expf(m0 - nm0);
            float cr1 = __expf(m1 - nm1);

            float rs0 = 0.0f, rs1 = 0.0f;
            #pragma unroll
            for (int nb = 0; nb < 8; ++nb) {
                float e0 = __expf(sf[nb][0] - nm0);
                float e1 = __expf(sf[nb][1] - nm0);
                float e2 = __expf(sf[nb][2] - nm1);
                float e3 = __expf(sf[nb][3] - nm1);
                rs0 += e0 + e1;
                rs1 += e2 + e3;
                *(float2*)(Ps + (r0 + g)     * PP + nb * 8 + 2 * tig) =
                    make_float2(f2tf_f(e0), f2tf_f(e1));
                *(float2*)(Ps + (r0 + g + 8) * PP + nb * 8 + 2 * tig) =
                    make_float2(f2tf_f(e2), f2tf_f(e3));
            }
            rs0 += __shfl_xor_sync(0xffffffffu, rs0, 1);
            rs0 += __shfl_xor_sync(0xffffffffu, rs0, 2);
            rs1 += __shfl_xor_sync(0xffffffffu, rs1, 1);
            rs1 += __shfl_xor_sync(0xffffffffu, rs1, 2);

            m0 = nm0; m1 = nm1;
            l0 = l0 * cr0 + rs0;
            l1 = l1 * cr1 + rs1;

            #pragma unroll
            for (int nb = 0; nb < 16; ++nb) {
                of[nb][0] *= cr0; of[nb][1] *= cr0;
                of[nb][2] *= cr1; of[nb][3] *= cr1;
            }
            __syncwarp();

            // ---- O += P V
            #pragma unroll
            for (int ks2 = 0; ks2 < 8; ++ks2) {
                uint32_t pa[4];
                pa[0] = __float_as_uint(Ps[(r0 + g)     * PP + ks2 * 8 + tig]);
                pa[1] = __float_as_uint(Ps[(r0 + g + 8) * PP + ks2 * 8 + tig]);
                pa[2] = __float_as_uint(Ps[(r0 + g)     * PP + ks2 * 8 + tig + 4]);
                pa[3] = __float_as_uint(Ps[(r0 + g + 8) * PP + ks2 * 8 + tig + 4]);
                #pragma unroll
                for (int nb = 0; nb < 16; ++nb) {
                    uint32_t vb[2];
                    vb[0] = __float_as_uint(Vs[(ks2 * 8 + tig)     * VP + nb * 8 + g]);
                    vb[1] = __float_as_uint(Vs[(ks2 * 8 + tig + 4) * VP + nb * 8 + g]);
                    mma_tf32(of[nb], pa, vb);
                }
            }
            __syncwarp();
        }
        __syncthreads();   // all warps done with buf (kt&1) before next prefetch lands
    }

    // ---- normalize and write y (tf32-rounded: proj GEMM consumes it directly)
    float inv0 = 1.0f / l0;
    float inv1 = 1.0f / l1;
    size_t yrow0 = (size_t)b * SEQ + rowg0;
    size_t yrow1 = (size_t)b * SEQ + rowg1;
    #pragma unroll
    for (int nb = 0; nb < 16; ++nb) {
        int col = h * HD + nb * 8 + 2 * tig;
        *(float2*)(y + yrow0 * CDIM + col) =
            make_float2(f2tf_f(of[nb][0] * inv0), f2tf_f(of[nb][1] * inv0));
        *(float2*)(y + yrow1 * CDIM + col) =
            make_float2(f2tf_f(of[nb][2] * inv1), f2tf_f(of[nb][3] * inv1));
    }
}

// ---------------------------------------------------------------------------
// kernel_launch
// ---------------------------------------------------------------------------
extern "C" void kernel_launch(void* const* d_in, const int* in_sizes, int n_in,
                              void* d_out, int out_size)
{
    const float* x     = (const float*)d_in[0];
    const float* Wqkv  = (const float*)d_in[1];
    const float* Wproj = (const float*)d_in[2];
    float* out = (float*)d_out;

    float *qkv, *y, *xtf, *wqkv, *wprj;
    cudaGetSymbolAddress((void**)&qkv,  g_qkv);
    cudaGetSymbolAddress((void**)&y,    g_y);
    cudaGetSymbolAddress((void**)&xtf,  g_xtf);
    cudaGetSymbolAddress((void**)&wqkv, g_wqkv);
    cudaGetSymbolAddress((void**)&wprj, g_wprj);

    cudaFuncSetAttribute(gemm_tf32<true>,
                         cudaFuncAttributeMaxDynamicSharedMemorySize,
                         GEMM_SMEM_BYTES);
    cudaFuncSetAttribute(gemm_tf32<false>,
                         cudaFuncAttributeMaxDynamicSharedMemorySize,
                         GEMM_SMEM_BYTES);
    cudaFuncSetAttribute(attn_tc,
                         cudaFuncAttributeMaxDynamicSharedMemorySize,
                         ATTN_SMEM_BYTES);

    // 0) round inputs to tf32 once
    {
        int n4x = MROWS * CDIM / 4;
        int n4q = CDIM * QKVDIM / 4;
        int n4p = CDIM * CDIM / 4;
        round_tf32<<<(n4x + 255) / 256, 256>>>(x,     xtf,  n4x);
        round_tf32<<<(n4q + 255) / 256, 256>>>(Wqkv,  wqkv, n4q);
        round_tf32<<<(n4p + 255) / 256, 256>>>(Wproj, wprj, n4p);
    }

    // 1) qkv = x @ Wqkv  (output tf32-rounded for attention)
    gemm_tf32<true><<<dim3(QKVDIM / BN, MROWS / BM), 256, GEMM_SMEM_BYTES>>>(
        xtf, wqkv, qkv, MROWS, QKVDIM, CDIM);

    // 2) attention -> y (tf32-rounded)
    attn_tc<<<dim3(SEQ / ABQ, NHEAD, BATCH), 256, ATTN_SMEM_BYTES>>>(qkv, y);

    // 3) out = y @ Wproj (full fp32 output)
    gemm_tf32<false><<<dim3(CDIM / BN, MROWS / BM), 256, GEMM_SMEM_BYTES>>>(
        y, wprj, out, MROWS, CDIM, CDIM);
}